// round 15
// baseline (speedup 1.0000x reference)
#include <cuda_runtime.h>
#include <cuda_bf16.h>
#include <cstdint>

#define BB 8
#define NN 10000
#define EE 160000
#define FF 64
#define BN (BB * NN)          // 80000 nodes
#define BE (BB * EE)          // 1280000 edges
#define SCAN_BLKS ((BN + 1023) / 1024)   // 79

#define FLAG_AGG    (1ULL << 62)
#define FLAG_PREFIX (2ULL << 62)
#define VAL_MASK    ((1ULL << 62) - 1)

typedef unsigned long long u64;
typedef unsigned int u32;

// ---- scratch (device globals; no allocation allowed) ----
__device__ int   g_is64;
__device__ int   g_degi[BN];
__device__ float g_dinv[BN];
__device__ int   g_rowstart[BN];
__device__ int   g_cursor[BN];
__device__ u64   g_state[SCAN_BLKS];
__device__ int2  g_csr[BE];            // {col, norm-bits} grouped by row
__device__ unsigned short g_tb[BN * FF];  // bf16 post-linear features
__device__ float g_pA[BN * FF];
__device__ float g_pB[BN * FF];

// ---------------------------------------------------------------------------
__device__ __forceinline__ u32 tf32c(float f) {
    u32 r;
    asm("cvt.rna.tf32.f32 %0, %1;" : "=r"(r) : "f"(f));
    return r;
}
__device__ __forceinline__ u64 packu(u32 lo, u32 hi) {
    return ((u64)hi << 32) | (u64)lo;
}

__device__ __forceinline__ void decode_edge(const void* ei, int e, int is64,
                                            int& r, int& c) {
    if (is64) {
        const long long* p = (const long long*)ei;
        r = (int)p[2 * e];
        c = (int)p[2 * e + 1];
    } else {
        const int* p = (const int*)ei;
        r = p[2 * e];
        c = p[2 * e + 1];
    }
    r = min(max(r, 0), NN - 1);
    c = min(max(c, 0), NN - 1);
    int b = e / EE;
    r += b * NN;
    c += b * NN;
}

// ---------------------------------------------------------------------------
__global__ void setup_k(const void* ei, int* __restrict__ degp) {
    int i = blockIdx.x * blockDim.x + threadIdx.x;
    for (; i < BN; i += gridDim.x * blockDim.x) degp[i] = 0;
    if (blockIdx.x == 0 && threadIdx.x < 32) {
        if (threadIdx.x < SCAN_BLKS) {
            g_state[threadIdx.x] = 0;
            if (threadIdx.x + 32 < SCAN_BLKS) g_state[threadIdx.x + 32] = 0;
            if (threadIdx.x + 64 < SCAN_BLKS) g_state[threadIdx.x + 64] = 0;
        }
        const long long* p = (const long long*)ei;
        long long v0 = p[threadIdx.x];
        long long v1 = p[threadIdx.x + 32];
        bool bad = (v0 < 0) | (v0 >= NN) | (v1 < 0) | (v1 >= NN);
        unsigned m = __ballot_sync(0xffffffffu, bad);
        if (threadIdx.x == 0) g_is64 = (m == 0) ? 1 : 0;
    }
}

// degree histogram
__global__ void edges_k(const void* __restrict__ ei) {
    int e = blockIdx.x * blockDim.x + threadIdx.x;
    if (e >= BE) return;
    int r, c;
    decode_edge(ei, e, g_is64, r, c);
    atomicAdd(&g_degi[r], 1);
}

// single-kernel decoupled-lookback scan; fused dinv + cursor init
__global__ void __launch_bounds__(1024, 1) scan_k() {
    __shared__ int warpsum[32];
    __shared__ int sTot;
    __shared__ u64 sBase;
    int tid = threadIdx.x, lane = tid & 31, wid = tid >> 5;
    int b = blockIdx.x;
    int i = b * 1024 + tid;

    int v = (i < BN) ? g_degi[i] : 0;
    int x = v;
#pragma unroll
    for (int off = 1; off < 32; off <<= 1) {
        int y = __shfl_up_sync(0xffffffffu, x, off);
        if (lane >= off) x += y;
    }
    if (lane == 31) warpsum[wid] = x;
    __syncthreads();

    if (wid == 0) {
        int s = warpsum[lane];
        int xs = s;
#pragma unroll
        for (int off = 1; off < 32; off <<= 1) {
            int y = __shfl_up_sync(0xffffffffu, xs, off);
            if (lane >= off) xs += y;
        }
        warpsum[lane] = xs - s;
        if (lane == 31) sTot = xs;
        __syncwarp();
        int tot = sTot;

        if (b == 0) {
            if (lane == 0) {
                sBase = 0;
                atomicExch(&g_state[0], FLAG_PREFIX | (u64)tot);
            }
        } else {
            if (lane == 0)
                atomicExch(&g_state[b], FLAG_AGG | (u64)tot);
            u64 run = 0;
            int j = b - 1;
            while (true) {
                int idx = j - lane;
                u64 s64;
                if (idx >= 0) {
                    do {
                        s64 = *(volatile u64*)&g_state[idx];
                    } while ((s64 >> 62) == 0);
                } else {
                    s64 = FLAG_PREFIX;
                }
                unsigned f = (unsigned)(s64 >> 62);
                u64 val = s64 & VAL_MASK;
                unsigned pm = __ballot_sync(0xffffffffu, f == 2);
                if (pm) {
                    int lp = __ffs(pm) - 1;
                    u64 c2 = (lane <= lp) ? val : 0;
#pragma unroll
                    for (int o = 16; o; o >>= 1)
                        c2 += __shfl_down_sync(0xffffffffu, c2, o);
                    run += __shfl_sync(0xffffffffu, c2, 0);
                    break;
                } else {
                    u64 c2 = val;
#pragma unroll
                    for (int o = 16; o; o >>= 1)
                        c2 += __shfl_down_sync(0xffffffffu, c2, o);
                    run += __shfl_sync(0xffffffffu, c2, 0);
                    j -= 32;
                }
            }
            if (lane == 0) {
                sBase = run;
                atomicExch(&g_state[b], FLAG_PREFIX | (run + (u64)tot));
            }
        }
    }
    __syncthreads();

    if (i < BN) {
        int start = (int)sBase + warpsum[wid] + (x - v);
        g_rowstart[i] = start;
        g_cursor[i]   = start;
        g_dinv[i] = v > 0 ? rsqrtf((float)v) : 0.f;
    }
}

// scatter edges into CSR slots
__global__ void fill_k(const void* __restrict__ ei) {
    int e = blockIdx.x * blockDim.x + threadIdx.x;
    if (e >= BE) return;
    int r, c;
    decode_edge(ei, e, g_is64, r, c);
    int pos = atomicAdd(&g_cursor[r], 1);
    float nm = g_dinv[r] * g_dinv[c];
    g_csr[pos] = make_int2(c, __float_as_int(nm));
}

// ---------------------------------------------------------------------------
// t = (relu?)(in) @ W^T + b -> bf16, via mma.sync.m16n8k8 tf32.
// Block: 256 thr = 8 warps in 2 (row) x 4 (col) grid over 32 rows.
// Each warp: 16 rows x 16 out-cols; W fragments preloaded in 32 regs;
// A staged in smem as paired-tf32 u64 [row][q*8+ks] (stride 33 -> uniform
// 2-per-bank LDS.64). 16 mma per warp. Bias via C-init.
template <bool RELU>
__global__ void __launch_bounds__(256)
linear_k(const float* __restrict__ in, const float* __restrict__ W,
         const float* __restrict__ bias, unsigned short* __restrict__ out) {
    __shared__ u64   sA[32 * 33];
    __shared__ float sb[64];
    int tid = threadIdx.x;
    int lane = tid & 31, w = tid >> 5;
    int wr = w >> 2, wc = w & 3;      // row-group 0..1, col-group 0..3
    int g = lane >> 2, q = lane & 3;  // groupID, threadID_in_group
    int row0 = blockIdx.x * 32;
    int n0 = wc * 16;

    if (tid < 64) sb[tid] = bias[tid];

    // --- preload B fragments (W in tf32), reused across all k-steps ---
    u32 bf0[2][8], bf1[2][8];
#pragma unroll
    for (int nt = 0; nt < 2; nt++)
#pragma unroll
        for (int ks = 0; ks < 8; ks++) {
            float w0 = __ldg(&W[(n0 + nt * 8 + g) * 64 + ks * 8 + q]);
            float w1 = __ldg(&W[(n0 + nt * 8 + g) * 64 + ks * 8 + q + 4]);
            bf0[nt][ks] = tf32c(w0);
            bf1[nt][ks] = tf32c(w1);
        }

    // --- stage A: thread (r, ks) converts 8 cols into 4 paired u64 ---
    {
        int r = tid >> 3, ks = tid & 7;
        const float4* xp = (const float4*)(in + (size_t)(row0 + r) * 64 + ks * 8);
        float4 v0 = xp[0], v1 = xp[1];
        if (RELU) {
            v0.x = fmaxf(v0.x, 0.f); v0.y = fmaxf(v0.y, 0.f);
            v0.z = fmaxf(v0.z, 0.f); v0.w = fmaxf(v0.w, 0.f);
            v1.x = fmaxf(v1.x, 0.f); v1.y = fmaxf(v1.y, 0.f);
            v1.z = fmaxf(v1.z, 0.f); v1.w = fmaxf(v1.w, 0.f);
        }
        u64* rowp = &sA[r * 33];
        rowp[0 * 8 + ks] = packu(tf32c(v0.x), tf32c(v1.x));
        rowp[1 * 8 + ks] = packu(tf32c(v0.y), tf32c(v1.y));
        rowp[2 * 8 + ks] = packu(tf32c(v0.z), tf32c(v1.z));
        rowp[3 * 8 + ks] = packu(tf32c(v0.w), tf32c(v1.w));
    }
    __syncthreads();

    // --- C init with bias ---
    float c0[2], c1[2], c2[2], c3[2];
#pragma unroll
    for (int nt = 0; nt < 2; nt++) {
        int cb = n0 + nt * 8 + 2 * q;
        c0[nt] = sb[cb];  c1[nt] = sb[cb + 1];
        c2[nt] = sb[cb];  c3[nt] = sb[cb + 1];
    }

    int rlo = wr * 16 + g, rhi = rlo + 8;
#pragma unroll
    for (int ks = 0; ks < 8; ks++) {
        u64 lo = sA[rlo * 33 + q * 8 + ks];
        u64 hi = sA[rhi * 33 + q * 8 + ks];
        u32 a0 = (u32)lo, a2 = (u32)(lo >> 32);
        u32 a1 = (u32)hi, a3 = (u32)(hi >> 32);
#pragma unroll
        for (int nt = 0; nt < 2; nt++) {
            asm volatile(
                "mma.sync.aligned.m16n8k8.row.col.f32.tf32.tf32.f32 "
                "{%0,%1,%2,%3}, {%4,%5,%6,%7}, {%8,%9}, {%0,%1,%2,%3};\n"
                : "+f"(c0[nt]), "+f"(c1[nt]), "+f"(c2[nt]), "+f"(c3[nt])
                : "r"(a0), "r"(a1), "r"(a2), "r"(a3),
                  "r"(bf0[nt][ks]), "r"(bf1[nt][ks]));
        }
    }

    // --- store: pack col pairs to bf16x2 ---
#pragma unroll
    for (int nt = 0; nt < 2; nt++) {
        int cb = n0 + nt * 8 + 2 * q;
        u32 p0, p1;
        asm("cvt.rn.bf16x2.f32 %0, %1, %2;" : "=r"(p0) : "f"(c1[nt]), "f"(c0[nt]));
        asm("cvt.rn.bf16x2.f32 %0, %1, %2;" : "=r"(p1) : "f"(c3[nt]), "f"(c2[nt]));
        *(u32*)&out[(size_t)(row0 + rlo) * 64 + cb] = p0;
        *(u32*)&out[(size_t)(row0 + rhi) * 64 + cb] = p1;
    }
}

// ---------------------------------------------------------------------------
// CSR gather SpMM over bf16 t (128B/edge). fp32 accumulate.
__global__ void __launch_bounds__(256)
spmm_k(const unsigned short* __restrict__ tb, float* __restrict__ out) {
    int warp = (blockIdx.x * blockDim.x + threadIdx.x) >> 5;
    if (warp >= BN) return;
    int lane = threadIdx.x & 31;
    int start = g_rowstart[warp];
    int cnt   = g_degi[warp];

    const u32* t32 = (const u32*)tb;
    float acc0 = 0.f, acc1 = 0.f;
    if (cnt > 0) {
        int2 m = __ldg(&g_csr[start]);
#pragma unroll 4
        for (int e = 0; e < cnt; e++) {
            int2 mn = (e + 1 < cnt) ? __ldg(&g_csr[start + e + 1]) : m;
            float nm = __int_as_float(m.y);
            u32 v = __ldg(t32 + (size_t)m.x * 32 + lane);
            acc0 = fmaf(nm, __uint_as_float(v << 16), acc0);
            acc1 = fmaf(nm, __uint_as_float(v & 0xffff0000u), acc1);
            m = mn;
        }
    }
    reinterpret_cast<float2*>(out + (size_t)warp * 64)[lane] =
        make_float2(acc0, acc1);
}

// ---------------------------------------------------------------------------
extern "C" void kernel_launch(void* const* d_in, const int* in_sizes, int n_in,
                              void* d_out, int out_size) {
    const float* x = nullptr;
    const void*  ei = nullptr;
    const float* Ws[3] = {nullptr, nullptr, nullptr};
    const float* bs[3] = {nullptr, nullptr, nullptr};
    int nW = 0, nb = 0;
    for (int i = 0; i < n_in; i++) {
        long long sz = in_sizes[i];
        if (sz == (long long)BN * FF)      x  = (const float*)d_in[i];
        else if (sz == (long long)BE * 2)  ei = d_in[i];
        else if (sz == FF * FF) { if (nW < 3) Ws[nW++] = (const float*)d_in[i]; }
        else if (sz == FF)      { if (nb < 3) bs[nb++] = (const float*)d_in[i]; }
    }
    float* out = (float*)d_out;

    int   *degi;
    unsigned short *tb;
    float *pA, *pB;
    cudaGetSymbolAddress((void**)&degi, g_degi);
    cudaGetSymbolAddress((void**)&tb,   g_tb);
    cudaGetSymbolAddress((void**)&pA,   g_pA);
    cudaGetSymbolAddress((void**)&pB,   g_pB);

    const int TPB = 256;
    const int edgeBlocks = (BE + TPB - 1) / TPB;     // 5000
    const int nodeBlocks = (BN + TPB - 1) / TPB;     // 313
    const int spmmBlocks = (BN * 32 + TPB - 1) / TPB;// 10000
    const int linBlocks  = BN / 32;                  // 2500

    setup_k<<<nodeBlocks, TPB>>>(ei, degi);                     // 0
    edges_k<<<edgeBlocks, TPB>>>(ei);                           // 1
    scan_k <<<SCAN_BLKS, 1024>>>();                             // 2
    linear_k<false><<<linBlocks, TPB>>>(x, Ws[0], bs[0], tb);   // 3 <- ncu
    fill_k <<<edgeBlocks, TPB>>>(ei);                           // 4
    spmm_k<<<spmmBlocks, TPB>>>(tb, pA);                        // 5
    linear_k<true ><<<linBlocks, TPB>>>(pA, Ws[1], bs[1], tb);  // 6
    spmm_k<<<spmmBlocks, TPB>>>(tb, pB);                        // 7
    linear_k<true ><<<linBlocks, TPB>>>(pB, Ws[2], bs[2], tb);  // 8
    spmm_k<<<spmmBlocks, TPB>>>(tb, out);                       // 9
}

// round 16
// speedup vs baseline: 1.1576x; 1.1576x over previous
#include <cuda_runtime.h>
#include <cuda_bf16.h>
#include <cstdint>

#define BB 8
#define NN 10000
#define EE 160000
#define FF 64
#define BN (BB * NN)          // 80000 nodes
#define BE (BB * EE)          // 1280000 edges
#define SCAN_BLKS ((BN + 1023) / 1024)   // 79

#define FLAG_AGG    (1ULL << 62)
#define FLAG_PREFIX (2ULL << 62)
#define VAL_MASK    ((1ULL << 62) - 1)

typedef unsigned long long u64;
typedef unsigned int u32;

// ---- scratch (device globals; no allocation allowed) ----
__device__ int   g_is64;
__device__ int   g_degi[BN];
__device__ float g_dinv[BN];
__device__ int   g_rowstart[BN];
__device__ int   g_cursor[BN];
__device__ u64   g_state[SCAN_BLKS];
__device__ int2  g_csr[BE];            // {col, norm-bits} grouped by row
__device__ unsigned short g_tb[BN * FF];  // bf16 post-linear features
__device__ float g_pA[BN * FF];
__device__ float g_pB[BN * FF];

// ---------------------------------------------------------------------------
__device__ __forceinline__ u32 tf32c(float f) {
    u32 r;
    asm("cvt.rna.tf32.f32 %0, %1;" : "=r"(r) : "f"(f));
    return r;
}
__device__ __forceinline__ u64 packu(u32 lo, u32 hi) {
    return ((u64)hi << 32) | (u64)lo;
}

__device__ __forceinline__ void decode_edge(const void* ei, int e, int is64,
                                            int& r, int& c) {
    if (is64) {
        const long long* p = (const long long*)ei;
        r = (int)p[2 * e];
        c = (int)p[2 * e + 1];
    } else {
        const int* p = (const int*)ei;
        r = p[2 * e];
        c = p[2 * e + 1];
    }
    r = min(max(r, 0), NN - 1);
    c = min(max(c, 0), NN - 1);
    int b = e / EE;
    r += b * NN;
    c += b * NN;
}

// ---------------------------------------------------------------------------
__global__ void setup_k(const void* ei, int* __restrict__ degp) {
    int i = blockIdx.x * blockDim.x + threadIdx.x;
    for (; i < BN; i += gridDim.x * blockDim.x) degp[i] = 0;
    if (blockIdx.x == 0 && threadIdx.x < 32) {
        if (threadIdx.x < SCAN_BLKS) {
            g_state[threadIdx.x] = 0;
            if (threadIdx.x + 32 < SCAN_BLKS) g_state[threadIdx.x + 32] = 0;
            if (threadIdx.x + 64 < SCAN_BLKS) g_state[threadIdx.x + 64] = 0;
        }
        const long long* p = (const long long*)ei;
        long long v0 = p[threadIdx.x];
        long long v1 = p[threadIdx.x + 32];
        bool bad = (v0 < 0) | (v0 >= NN) | (v1 < 0) | (v1 >= NN);
        unsigned m = __ballot_sync(0xffffffffu, bad);
        if (threadIdx.x == 0) g_is64 = (m == 0) ? 1 : 0;
    }
}

// degree histogram
__global__ void edges_k(const void* __restrict__ ei) {
    int e = blockIdx.x * blockDim.x + threadIdx.x;
    if (e >= BE) return;
    int r, c;
    decode_edge(ei, e, g_is64, r, c);
    atomicAdd(&g_degi[r], 1);
}

// single-kernel decoupled-lookback scan; fused dinv + cursor init
__global__ void __launch_bounds__(1024, 1) scan_k() {
    __shared__ int warpsum[32];
    __shared__ int sTot;
    __shared__ u64 sBase;
    int tid = threadIdx.x, lane = tid & 31, wid = tid >> 5;
    int b = blockIdx.x;
    int i = b * 1024 + tid;

    int v = (i < BN) ? g_degi[i] : 0;
    int x = v;
#pragma unroll
    for (int off = 1; off < 32; off <<= 1) {
        int y = __shfl_up_sync(0xffffffffu, x, off);
        if (lane >= off) x += y;
    }
    if (lane == 31) warpsum[wid] = x;
    __syncthreads();

    if (wid == 0) {
        int s = warpsum[lane];
        int xs = s;
#pragma unroll
        for (int off = 1; off < 32; off <<= 1) {
            int y = __shfl_up_sync(0xffffffffu, xs, off);
            if (lane >= off) xs += y;
        }
        warpsum[lane] = xs - s;
        if (lane == 31) sTot = xs;
        __syncwarp();
        int tot = sTot;

        if (b == 0) {
            if (lane == 0) {
                sBase = 0;
                atomicExch(&g_state[0], FLAG_PREFIX | (u64)tot);
            }
        } else {
            if (lane == 0)
                atomicExch(&g_state[b], FLAG_AGG | (u64)tot);
            u64 run = 0;
            int j = b - 1;
            while (true) {
                int idx = j - lane;
                u64 s64;
                if (idx >= 0) {
                    do {
                        s64 = *(volatile u64*)&g_state[idx];
                    } while ((s64 >> 62) == 0);
                } else {
                    s64 = FLAG_PREFIX;
                }
                unsigned f = (unsigned)(s64 >> 62);
                u64 val = s64 & VAL_MASK;
                unsigned pm = __ballot_sync(0xffffffffu, f == 2);
                if (pm) {
                    int lp = __ffs(pm) - 1;
                    u64 c2 = (lane <= lp) ? val : 0;
#pragma unroll
                    for (int o = 16; o; o >>= 1)
                        c2 += __shfl_down_sync(0xffffffffu, c2, o);
                    run += __shfl_sync(0xffffffffu, c2, 0);
                    break;
                } else {
                    u64 c2 = val;
#pragma unroll
                    for (int o = 16; o; o >>= 1)
                        c2 += __shfl_down_sync(0xffffffffu, c2, o);
                    run += __shfl_sync(0xffffffffu, c2, 0);
                    j -= 32;
                }
            }
            if (lane == 0) {
                sBase = run;
                atomicExch(&g_state[b], FLAG_PREFIX | (run + (u64)tot));
            }
        }
    }
    __syncthreads();

    if (i < BN) {
        int start = (int)sBase + warpsum[wid] + (x - v);
        g_rowstart[i] = start;
        g_cursor[i]   = start;
        g_dinv[i] = v > 0 ? rsqrtf((float)v) : 0.f;
    }
}

// scatter edges into CSR slots
__global__ void fill_k(const void* __restrict__ ei) {
    int e = blockIdx.x * blockDim.x + threadIdx.x;
    if (e >= BE) return;
    int r, c;
    decode_edge(ei, e, g_is64, r, c);
    int pos = atomicAdd(&g_cursor[r], 1);
    float nm = g_dinv[r] * g_dinv[c];
    g_csr[pos] = make_int2(c, __float_as_int(nm));
}

// ---------------------------------------------------------------------------
// t = (relu?)(in) @ W^T + b -> bf16, via mma.sync.m16n8k8 tf32.
// 128 rows/block as 4 ping-pong tiles of 32; W fragments + bias loaded ONCE
// per block (amortizes the scattered W preload 4x vs R15). One sync/tile:
// mma(t) precedes sync(t+1) precedes stage(t+2) -> no WAR hazard.
template <bool RELU>
__global__ void __launch_bounds__(256)
linear_k(const float* __restrict__ in, const float* __restrict__ W,
         const float* __restrict__ bias, unsigned short* __restrict__ out) {
    __shared__ u64   sA[2][32 * 33];
    __shared__ float sb[64];
    int tid = threadIdx.x;
    int lane = tid & 31, w = tid >> 5;
    int wr = w >> 2, wc = w & 3;      // row-group 0..1, col-group 0..3
    int g = lane >> 2, q = lane & 3;  // groupID, threadID_in_group
    int blk0 = blockIdx.x * 128;
    int n0 = wc * 16;

    if (tid < 64) sb[tid] = bias[tid];

    // --- preload B fragments (W in tf32) once per block ---
    u32 bf0[2][8], bf1[2][8];
#pragma unroll
    for (int nt = 0; nt < 2; nt++)
#pragma unroll
        for (int ks = 0; ks < 8; ks++) {
            float w0 = __ldg(&W[(n0 + nt * 8 + g) * 64 + ks * 8 + q]);
            float w1 = __ldg(&W[(n0 + nt * 8 + g) * 64 + ks * 8 + q + 4]);
            bf0[nt][ks] = tf32c(w0);
            bf1[nt][ks] = tf32c(w1);
        }

    int sr = tid >> 3, sks = tid & 7;   // staging coords
    int rlo = wr * 16 + g, rhi = rlo + 8;

#pragma unroll
    for (int tile = 0; tile < 4; tile++) {
        u64* buf = sA[tile & 1];
        int row0 = blk0 + tile * 32;

        // --- stage A tile: thread (sr, sks) converts 8 cols -> 4 paired u64
        {
            const float4* xp =
                (const float4*)(in + (size_t)(row0 + sr) * 64 + sks * 8);
            float4 v0 = xp[0], v1 = xp[1];
            if (RELU) {
                v0.x = fmaxf(v0.x, 0.f); v0.y = fmaxf(v0.y, 0.f);
                v0.z = fmaxf(v0.z, 0.f); v0.w = fmaxf(v0.w, 0.f);
                v1.x = fmaxf(v1.x, 0.f); v1.y = fmaxf(v1.y, 0.f);
                v1.z = fmaxf(v1.z, 0.f); v1.w = fmaxf(v1.w, 0.f);
            }
            u64* rowp = &buf[sr * 33];
            rowp[0 * 8 + sks] = packu(tf32c(v0.x), tf32c(v1.x));
            rowp[1 * 8 + sks] = packu(tf32c(v0.y), tf32c(v1.y));
            rowp[2 * 8 + sks] = packu(tf32c(v0.z), tf32c(v1.z));
            rowp[3 * 8 + sks] = packu(tf32c(v0.w), tf32c(v1.w));
        }
        __syncthreads();

        // --- C init with bias ---
        float c0[2], c1[2], c2[2], c3[2];
#pragma unroll
        for (int nt = 0; nt < 2; nt++) {
            int cb = n0 + nt * 8 + 2 * q;
            c0[nt] = sb[cb];  c1[nt] = sb[cb + 1];
            c2[nt] = sb[cb];  c3[nt] = sb[cb + 1];
        }

#pragma unroll
        for (int ks = 0; ks < 8; ks++) {
            u64 lo = buf[rlo * 33 + q * 8 + ks];
            u64 hi = buf[rhi * 33 + q * 8 + ks];
            u32 a0 = (u32)lo, a2 = (u32)(lo >> 32);
            u32 a1 = (u32)hi, a3 = (u32)(hi >> 32);
#pragma unroll
            for (int nt = 0; nt < 2; nt++) {
                asm volatile(
                    "mma.sync.aligned.m16n8k8.row.col.f32.tf32.tf32.f32 "
                    "{%0,%1,%2,%3}, {%4,%5,%6,%7}, {%8,%9}, {%0,%1,%2,%3};\n"
                    : "+f"(c0[nt]), "+f"(c1[nt]), "+f"(c2[nt]), "+f"(c3[nt])
                    : "r"(a0), "r"(a1), "r"(a2), "r"(a3),
                      "r"(bf0[nt][ks]), "r"(bf1[nt][ks]));
            }
        }

        // --- store: pack col pairs to bf16x2 ---
#pragma unroll
        for (int nt = 0; nt < 2; nt++) {
            int cb = n0 + nt * 8 + 2 * q;
            u32 p0, p1;
            asm("cvt.rn.bf16x2.f32 %0, %1, %2;" : "=r"(p0) : "f"(c1[nt]), "f"(c0[nt]));
            asm("cvt.rn.bf16x2.f32 %0, %1, %2;" : "=r"(p1) : "f"(c3[nt]), "f"(c2[nt]));
            *(u32*)&out[(size_t)(row0 + rlo) * 64 + cb] = p0;
            *(u32*)&out[(size_t)(row0 + rhi) * 64 + cb] = p1;
        }
    }
}

// ---------------------------------------------------------------------------
// CSR gather SpMM over bf16 t (128B/edge). fp32 accumulate.
__global__ void __launch_bounds__(256)
spmm_k(const unsigned short* __restrict__ tb, float* __restrict__ out) {
    int warp = (blockIdx.x * blockDim.x + threadIdx.x) >> 5;
    if (warp >= BN) return;
    int lane = threadIdx.x & 31;
    int start = g_rowstart[warp];
    int cnt   = g_degi[warp];

    const u32* t32 = (const u32*)tb;
    float acc0 = 0.f, acc1 = 0.f;
    if (cnt > 0) {
        int2 m = __ldg(&g_csr[start]);
#pragma unroll 4
        for (int e = 0; e < cnt; e++) {
            int2 mn = (e + 1 < cnt) ? __ldg(&g_csr[start + e + 1]) : m;
            float nm = __int_as_float(m.y);
            u32 v = __ldg(t32 + (size_t)m.x * 32 + lane);
            acc0 = fmaf(nm, __uint_as_float(v << 16), acc0);
            acc1 = fmaf(nm, __uint_as_float(v & 0xffff0000u), acc1);
            m = mn;
        }
    }
    reinterpret_cast<float2*>(out + (size_t)warp * 64)[lane] =
        make_float2(acc0, acc1);
}

// ---------------------------------------------------------------------------
extern "C" void kernel_launch(void* const* d_in, const int* in_sizes, int n_in,
                              void* d_out, int out_size) {
    const float* x = nullptr;
    const void*  ei = nullptr;
    const float* Ws[3] = {nullptr, nullptr, nullptr};
    const float* bs[3] = {nullptr, nullptr, nullptr};
    int nW = 0, nb = 0;
    for (int i = 0; i < n_in; i++) {
        long long sz = in_sizes[i];
        if (sz == (long long)BN * FF)      x  = (const float*)d_in[i];
        else if (sz == (long long)BE * 2)  ei = d_in[i];
        else if (sz == FF * FF) { if (nW < 3) Ws[nW++] = (const float*)d_in[i]; }
        else if (sz == FF)      { if (nb < 3) bs[nb++] = (const float*)d_in[i]; }
    }
    float* out = (float*)d_out;

    int   *degi;
    unsigned short *tb;
    float *pA, *pB;
    cudaGetSymbolAddress((void**)&degi, g_degi);
    cudaGetSymbolAddress((void**)&tb,   g_tb);
    cudaGetSymbolAddress((void**)&pA,   g_pA);
    cudaGetSymbolAddress((void**)&pB,   g_pB);

    const int TPB = 256;
    const int edgeBlocks = (BE + TPB - 1) / TPB;     // 5000
    const int nodeBlocks = (BN + TPB - 1) / TPB;     // 313
    const int spmmBlocks = (BN * 32 + TPB - 1) / TPB;// 10000
    const int linBlocks  = BN / 128;                 // 625

    setup_k<<<nodeBlocks, TPB>>>(ei, degi);                     // 0
    edges_k<<<edgeBlocks, TPB>>>(ei);                           // 1
    scan_k <<<SCAN_BLKS, 1024>>>();                             // 2
    linear_k<false><<<linBlocks, TPB>>>(x, Ws[0], bs[0], tb);   // 3 <- ncu
    fill_k <<<edgeBlocks, TPB>>>(ei);                           // 4
    spmm_k<<<spmmBlocks, TPB>>>(tb, pA);                        // 5
    linear_k<true ><<<linBlocks, TPB>>>(pA, Ws[1], bs[1], tb);  // 6
    spmm_k<<<spmmBlocks, TPB>>>(tb, pB);                        // 7
    linear_k<true ><<<linBlocks, TPB>>>(pB, Ws[2], bs[2], tb);  // 8
    spmm_k<<<spmmBlocks, TPB>>>(tb, out);                       // 9
}